// round 2
// baseline (speedup 1.0000x reference)
#include <cuda_runtime.h>
#include <cstdint>
#include <cstddef>

// Problem constants (fixed shapes)
#define NH   5000
#define NO   15000
#define NN   20000          // NH + NO
#define DD   1024
#define E_HH 20000
#define E_OO 40000
#define E_HO 40000
#define E_TOT 100000

#define FLAG_ACC  1
#define FLAG_RELU 2

// ---------------- static scratch (no allocations allowed) ----------------
__device__ float g_u_hh[(size_t)NH * DD];
__device__ float g_v_hh[(size_t)NH * DD];
__device__ float g_u_oo[(size_t)NO * DD];
__device__ float g_v_oo[(size_t)NO * DD];
__device__ float g_u_ho[(size_t)NH * DD];
__device__ float g_v_ho[(size_t)NO * DD];
__device__ float g_z  [(size_t)NN * DD];
__device__ float g_a  [E_TOT];
__device__ int   g_esrc[E_TOT];
__device__ int   g_edst[E_TOT];
__device__ int   g_eidx[E_TOT];
__device__ int   g_deg [NN];
__device__ int   g_off [NN + 1];
__device__ int   g_cur [NN];

// ---------------- SGEMM: C[M,1024] = A[M,1024] @ B[1024,1024] ------------
// B row-major (stride 1024). Optional accumulate into C, bias add, relu.
// 128x128 tile, BK=8, 256 threads, 8x8 per thread in split 4+4 layout.
#define BM 128
#define BN 128
#define BK 8

__global__ __launch_bounds__(256) void sgemm1024(
    const float* __restrict__ A, const float* __restrict__ B,
    float* __restrict__ C, int M,
    const float* __restrict__ bias, int flags)
{
    const int N = 1024, K = 1024;
    __shared__ float As[BK][BM];
    __shared__ float Bs[BK][BN];

    int tid = threadIdx.x;
    int bx = blockIdx.x, by = blockIdx.y;
    int tx = tid & 15;         // 0..15
    int ty = tid >> 4;         // 0..15

    int a_row = tid >> 1;            // 0..127
    int a_col = (tid & 1) << 2;      // 0 or 4
    int b_row = tid >> 5;            // 0..7
    int b_col = (tid & 31) << 2;     // 0..124

    int m0 = by * BM;
    const float* Ablk = A + (size_t)m0 * K;
    const float* Bblk = B + bx * BN;

    float acc[8][8];
#pragma unroll
    for (int i = 0; i < 8; i++)
#pragma unroll
        for (int j = 0; j < 8; j++) acc[i][j] = 0.f;

    for (int k0 = 0; k0 < K; k0 += BK) {
        float4 av = make_float4(0.f, 0.f, 0.f, 0.f);
        if (m0 + a_row < M)
            av = *(const float4*)(Ablk + (size_t)a_row * K + k0 + a_col);
        As[a_col + 0][a_row] = av.x;
        As[a_col + 1][a_row] = av.y;
        As[a_col + 2][a_row] = av.z;
        As[a_col + 3][a_row] = av.w;
        *(float4*)&Bs[b_row][b_col] =
            *(const float4*)(Bblk + (size_t)(k0 + b_row) * N + b_col);
        __syncthreads();

#pragma unroll
        for (int k = 0; k < BK; k++) {
            float4 a0 = *(const float4*)&As[k][ty * 4];
            float4 a1 = *(const float4*)&As[k][64 + ty * 4];
            float4 b0 = *(const float4*)&Bs[k][tx * 4];
            float4 b1 = *(const float4*)&Bs[k][64 + tx * 4];
            float ar[8] = {a0.x, a0.y, a0.z, a0.w, a1.x, a1.y, a1.z, a1.w};
            float br[8] = {b0.x, b0.y, b0.z, b0.w, b1.x, b1.y, b1.z, b1.w};
#pragma unroll
            for (int i = 0; i < 8; i++)
#pragma unroll
                for (int j = 0; j < 8; j++)
                    acc[i][j] += ar[i] * br[j];
        }
        __syncthreads();
    }

    // epilogue: rows {ty*4+ii, 64+ty*4+ii}, cols {tx*4.., 64+tx*4..}
#pragma unroll
    for (int hi = 0; hi < 2; hi++) {
#pragma unroll
        for (int ii = 0; ii < 4; ii++) {
            int gm = m0 + hi * 64 + ty * 4 + ii;
            if (gm >= M) continue;
            int r = hi * 4 + ii;
            float* crow = C + (size_t)gm * N + bx * BN;
#pragma unroll
            for (int hj = 0; hj < 2; hj++) {
                int cn = hj * 64 + tx * 4;
                float4 v = make_float4(acc[r][hj * 4 + 0], acc[r][hj * 4 + 1],
                                       acc[r][hj * 4 + 2], acc[r][hj * 4 + 3]);
                if (flags & FLAG_ACC) {
                    float4 c = *(const float4*)(crow + cn);
                    v.x += c.x; v.y += c.y; v.z += c.z; v.w += c.w;
                }
                if (bias) {
                    const float* bp = bias + bx * BN + cn;
                    v.x += bp[0]; v.y += bp[1]; v.z += bp[2]; v.w += bp[3];
                }
                if (flags & FLAG_RELU) {
                    v.x = fmaxf(v.x, 0.f); v.y = fmaxf(v.y, 0.f);
                    v.z = fmaxf(v.z, 0.f); v.w = fmaxf(v.w, 0.f);
                }
                *(float4*)(crow + cn) = v;
            }
        }
    }
}

// ---------------- edge bookkeeping ----------------
__global__ void build_edges_kernel(
    const int* __restrict__ shh, const int* __restrict__ dhh,
    const int* __restrict__ soo, const int* __restrict__ doo,
    const int* __restrict__ sho, const int* __restrict__ dho)
{
    int e = blockIdx.x * blockDim.x + threadIdx.x;
    if (e >= E_TOT) return;
    if (e < E_HH)               { g_esrc[e] = shh[e];             g_edst[e] = dhh[e]; }
    else if (e < E_HH + E_OO)   { g_esrc[e] = soo[e - E_HH];      g_edst[e] = doo[e - E_HH]; }
    else                        { g_esrc[e] = sho[e - E_HH - E_OO]; g_edst[e] = dho[e - E_HH - E_OO]; }
}

__global__ void hist_deg_kernel()
{
    int e = blockIdx.x * blockDim.x + threadIdx.x;
    if (e < E_TOT) atomicAdd(&g_deg[g_edst[e]], 1);
}

__global__ void scan_deg_kernel()
{
    __shared__ int sh[1024];
    int tid = threadIdx.x;
    int carry = 0;
    if (tid == 0) g_off[0] = 0;
    for (int base = 0; base < NN; base += 1024) {
        int i = base + tid;
        int v = (i < NN) ? g_deg[i] : 0;
        sh[tid] = v;
        __syncthreads();
        for (int s = 1; s < 1024; s <<= 1) {
            int t = (tid >= s) ? sh[tid - s] : 0;
            __syncthreads();
            sh[tid] += t;
            __syncthreads();
        }
        if (i < NN) g_off[i + 1] = carry + sh[tid];
        carry += sh[1023];
        __syncthreads();
    }
}

__global__ void copy_cur_kernel()
{
    int i = blockIdx.x * blockDim.x + threadIdx.x;
    if (i < NN) g_cur[i] = g_off[i];
}

__global__ void scatter_kernel()
{
    int e = blockIdx.x * blockDim.x + threadIdx.x;
    if (e >= E_TOT) return;
    int p = atomicAdd(&g_cur[g_edst[e]], 1);
    g_eidx[p] = e;
}

// ---------------- attention logits: a[e] = relu(u+v) . W_att + b --------
__global__ void edge_logits_kernel(const float* __restrict__ W_att,
                                   const float* __restrict__ b_att)
{
    int gw = (blockIdx.x * blockDim.x + threadIdx.x) >> 5;
    int lane = threadIdx.x & 31;
    if (gw >= E_TOT) return;
    int e = gw;
    int src = g_esrc[e], dst = g_edst[e];
    const float *u, *v;
    if (e < E_HH) {
        u = g_u_hh + (size_t)src * DD;
        v = g_v_hh + (size_t)dst * DD;
    } else if (e < E_HH + E_OO) {
        u = g_u_oo + (size_t)(src - NH) * DD;
        v = g_v_oo + (size_t)(dst - NH) * DD;
    } else {
        u = g_u_ho + (size_t)src * DD;
        v = g_v_ho + (size_t)(dst - NH) * DD;
    }
    float sum = 0.f;
    for (int d = lane * 4; d < DD; d += 128) {
        float4 uu = *(const float4*)(u + d);
        float4 vv = *(const float4*)(v + d);
        float4 ww = *(const float4*)(W_att + d);
        sum += fmaxf(uu.x + vv.x, 0.f) * ww.x
             + fmaxf(uu.y + vv.y, 0.f) * ww.y
             + fmaxf(uu.z + vv.z, 0.f) * ww.z
             + fmaxf(uu.w + vv.w, 0.f) * ww.w;
    }
#pragma unroll
    for (int o = 16; o > 0; o >>= 1)
        sum += __shfl_xor_sync(0xffffffffu, sum, o);
    if (lane == 0) g_a[e] = sum + b_att[0];
}

// ---------------- per-dst softmax + weighted aggregation into z ----------
__global__ __launch_bounds__(128) void softmax_z_kernel(const float* __restrict__ n_f)
{
    int n = blockIdx.x;
    int tid = threadIdx.x;
    int s0 = g_off[n], s1 = g_off[n + 1];
    float* zrow = g_z + (size_t)n * DD;

    if (s1 == s0) {
        float4 zf = make_float4(0.f, 0.f, 0.f, 0.f);
        for (int d = tid * 4; d < DD; d += 512)
            *(float4*)(zrow + d) = zf;
        return;
    }

    __shared__ float red[128];

    float m = -1e30f;
    for (int i = s0 + tid; i < s1; i += 128)
        m = fmaxf(m, g_a[g_eidx[i]]);
    red[tid] = m;
    __syncthreads();
    for (int s = 64; s > 0; s >>= 1) {
        if (tid < s) red[tid] = fmaxf(red[tid], red[tid + s]);
        __syncthreads();
    }
    float mx = red[0];
    __syncthreads();

    float se = 0.f;
    for (int i = s0 + tid; i < s1; i += 128)
        se += expf(g_a[g_eidx[i]] - mx);
    red[tid] = se;
    __syncthreads();
    for (int s = 64; s > 0; s >>= 1) {
        if (tid < s) red[tid] += red[tid + s];
        __syncthreads();
    }
    float inv = 1.f / red[0];

    float4 acc0 = make_float4(0.f, 0.f, 0.f, 0.f);
    float4 acc1 = make_float4(0.f, 0.f, 0.f, 0.f);
    for (int i = s0; i < s1; i++) {
        int e = g_eidx[i];
        float w = expf(g_a[e] - mx) * inv;
        const float* row = n_f + (size_t)g_esrc[e] * DD;
        float4 x0 = *(const float4*)(row + tid * 4);
        float4 x1 = *(const float4*)(row + 512 + tid * 4);
        acc0.x += w * x0.x; acc0.y += w * x0.y; acc0.z += w * x0.z; acc0.w += w * x0.w;
        acc1.x += w * x1.x; acc1.y += w * x1.y; acc1.z += w * x1.z; acc1.w += w * x1.w;
    }
    *(float4*)(zrow + tid * 4) = acc0;
    *(float4*)(zrow + 512 + tid * 4) = acc1;
}

// ---------------- launch ----------------
extern "C" void kernel_launch(void* const* d_in, const int* in_sizes, int n_in,
                              void* d_out, int out_size)
{
    const float* n_f    = (const float*)d_in[0];
    const int*   src_hh = (const int*)d_in[1];
    const int*   dst_hh = (const int*)d_in[2];
    const int*   src_oo = (const int*)d_in[3];
    const int*   dst_oo = (const int*)d_in[4];
    const int*   src_ho = (const int*)d_in[5];
    const int*   dst_ho = (const int*)d_in[6];
    const float* W_hh   = (const float*)d_in[7];
    const float* b_hh   = (const float*)d_in[8];
    const float* W_oo   = (const float*)d_in[9];
    const float* b_oo   = (const float*)d_in[10];
    const float* W_ho   = (const float*)d_in[11];
    const float* b_ho   = (const float*)d_in[12];
    const float* W_att  = (const float*)d_in[13];
    const float* b_att  = (const float*)d_in[14];
    const float* W_hn   = (const float*)d_in[15];
    const float* b_hn   = (const float*)d_in[16];
    const float* W_on   = (const float*)d_in[17];
    const float* b_on   = (const float*)d_in[18];
    float* out = (float*)d_out;

    void* p;
    float *u_hh, *v_hh, *u_oo, *v_oo, *u_ho, *v_ho, *z;
    int* deg;
    cudaGetSymbolAddress(&p, g_u_hh); u_hh = (float*)p;
    cudaGetSymbolAddress(&p, g_v_hh); v_hh = (float*)p;
    cudaGetSymbolAddress(&p, g_u_oo); u_oo = (float*)p;
    cudaGetSymbolAddress(&p, g_v_oo); v_oo = (float*)p;
    cudaGetSymbolAddress(&p, g_u_ho); u_ho = (float*)p;
    cudaGetSymbolAddress(&p, g_v_ho); v_ho = (float*)p;
    cudaGetSymbolAddress(&p, g_z);    z    = (float*)p;
    cudaGetSymbolAddress(&p, g_deg);  deg  = (int*)p;

    const size_t WOFF = (size_t)DD * DD;   // offset to bottom half of [2D,D] weight
    dim3 thr(256);
    auto grid = [](int M) { return dim3(8, (M + BM - 1) / BM); };

    // node projections: u = A @ W_top ; v = A @ W_bot + b
    sgemm1024<<<grid(NH), thr>>>(n_f,                 W_hh,        u_hh, NH, nullptr, 0);
    sgemm1024<<<grid(NH), thr>>>(n_f,                 W_hh + WOFF, v_hh, NH, b_hh,   0);
    sgemm1024<<<grid(NO), thr>>>(n_f + (size_t)NH*DD, W_oo,        u_oo, NO, nullptr, 0);
    sgemm1024<<<grid(NO), thr>>>(n_f + (size_t)NH*DD, W_oo + WOFF, v_oo, NO, b_oo,   0);
    sgemm1024<<<grid(NH), thr>>>(n_f,                 W_ho,        u_ho, NH, nullptr, 0);
    sgemm1024<<<grid(NO), thr>>>(n_f + (size_t)NH*DD, W_ho + WOFF, v_ho, NO, b_ho,   0);

    // independent: first half of the node-update MLPs (n_f part), into d_out
    sgemm1024<<<grid(NH), thr>>>(n_f,                 W_hn, out,                  NH, nullptr, 0);
    sgemm1024<<<grid(NO), thr>>>(n_f + (size_t)NH*DD, W_on, out + (size_t)NH*DD, NO, nullptr, 0);

    // CSR by destination
    build_edges_kernel<<<(E_TOT + 255) / 256, 256>>>(src_hh, dst_hh, src_oo, dst_oo, src_ho, dst_ho);
    cudaMemsetAsync(deg, 0, NN * sizeof(int));
    hist_deg_kernel<<<(E_TOT + 255) / 256, 256>>>();
    scan_deg_kernel<<<1, 1024>>>();
    copy_cur_kernel<<<(NN + 255) / 256, 256>>>();
    scatter_kernel<<<(E_TOT + 255) / 256, 256>>>();

    // attention logits + softmax-weighted aggregation
    edge_logits_kernel<<<(E_TOT * 32 + 255) / 256, 256>>>(W_att, b_att);
    softmax_z_kernel<<<NN, 128>>>(n_f);

    // second half of the node-update MLPs (z part), accumulate + bias + relu
    sgemm1024<<<grid(NH), thr>>>(z,                 W_hn + WOFF, out,                  NH, b_hn, FLAG_ACC | FLAG_RELU);
    sgemm1024<<<grid(NO), thr>>>(z + (size_t)NH*DD, W_on + WOFF, out + (size_t)NH*DD, NO, b_on, FLAG_ACC | FLAG_RELU);
}

// round 6
// speedup vs baseline: 3.0840x; 3.0840x over previous
#include <cuda_runtime.h>
#include <cstdint>
#include <cstddef>

// Problem constants (fixed shapes)
#define NH   5000
#define NO   15000
#define NN   20000          // NH + NO
#define DD   1024
#define E_HH 20000
#define E_OO 40000
#define E_HO 40000
#define E_TOT 100000

#define FLAG_ACC  1
#define FLAG_RELU 2

// ---------------- static scratch (no allocations allowed) ----------------
__device__ float g_u_hh[(size_t)NH * DD];
__device__ float g_v_hh[(size_t)NH * DD];
__device__ float g_u_oo[(size_t)NO * DD];
__device__ float g_v_oo[(size_t)NO * DD];
__device__ float g_u_ho[(size_t)NH * DD];
__device__ float g_v_ho[(size_t)NO * DD];
__device__ float g_z  [(size_t)NN * DD];
__device__ float g_a  [E_TOT];
__device__ int   g_esrc[E_TOT];
__device__ int   g_edst[E_TOT];
__device__ int   g_eidx[E_TOT];
__device__ int   g_deg [NN];
__device__ int   g_off [NN + 1];
__device__ int   g_cur [NN];

// ================= TF32 tensor-core SGEMM =================
// C[M,1024] (+)= A[M,1024] @ B[1024,1024], optional bias + relu.
// 128x128x32 CTA tile, 256 threads = 8 warps (2x4), each warp 64x32 via
// 4x4 m16n8k8 tf32 mma fragments. cp.async.cg double-buffered pipeline.
// Shared layouts padded for conflict-free fragment LDS:
//   As[m][k]: stride 36 floats  -> bank (4m+k)%32 all distinct in a warp
//   Bs[k][n]: stride 136 floats -> bank (8k+n)%32 all distinct in a warp

#define BM 128
#define BN 128
#define BK 32
#define ASTR 36
#define BSTR 136
#define ASZ (BM * ASTR)          // floats
#define BSZ (BK * BSTR)          // floats
#define SMEM_BYTES (2 * (ASZ + BSZ) * 4)

__device__ __forceinline__ uint32_t f2tf(float x) {
    uint32_t u;
    asm("cvt.rna.tf32.f32 %0, %1;" : "=r"(u) : "f"(x));
    return u;
}

__device__ __forceinline__ void mma_tf32(float* c, const uint32_t* a, const uint32_t* b) {
    asm volatile(
        "mma.sync.aligned.m16n8k8.row.col.f32.tf32.tf32.f32 "
        "{%0,%1,%2,%3}, {%4,%5,%6,%7}, {%8,%9}, {%0,%1,%2,%3};\n"
        : "+f"(c[0]), "+f"(c[1]), "+f"(c[2]), "+f"(c[3])
        : "r"(a[0]), "r"(a[1]), "r"(a[2]), "r"(a[3]), "r"(b[0]), "r"(b[1]));
}

__global__ __launch_bounds__(256) void sgemm_tf32(
    const float* __restrict__ A, const float* __restrict__ B,
    float* __restrict__ C, int M,
    const float* __restrict__ bias, int flags)
{
    extern __shared__ float sm[];
    const int tid  = threadIdx.x;
    const int lane = tid & 31;
    const int w    = tid >> 5;
    const int wm   = (w >> 2) * 64;   // warp row offset in tile
    const int wn   = (w & 3) * 32;    // warp col offset in tile
    const int g    = lane >> 2;       // group id 0..7
    const int tg   = lane & 3;        // thread-in-group 0..3

    const int m0 = blockIdx.y * BM;
    const int n0 = blockIdx.x * BN;

    float acc[4][4][4];
#pragma unroll
    for (int mt = 0; mt < 4; mt++)
#pragma unroll
        for (int nt = 0; nt < 4; nt++)
#pragma unroll
            for (int r = 0; r < 4; r++) acc[mt][nt][r] = 0.f;

    auto load_tile = [&](int k0, int buf) {
        float* As = sm + buf * (ASZ + BSZ);
        float* Bs = As + ASZ;
        const float* Ag = A + (size_t)m0 * 1024 + k0;
        const float* Bg = B + (size_t)k0 * 1024 + n0;
#pragma unroll
        for (int i = 0; i < 4; i++) {
            int q = tid + i * 256;            // 0..1023
            int r = q >> 3;                   // 0..127
            int c = (q & 7) << 2;             // 0..28 step 4
            uint32_t dst = (uint32_t)__cvta_generic_to_shared(As + r * ASTR + c);
            const float* src = Ag + (size_t)r * 1024 + c;
            int sz = (m0 + r < M) ? 16 : 0;   // zero-fill OOB rows
            asm volatile("cp.async.cg.shared.global [%0], [%1], 16, %2;\n"
                         :: "r"(dst), "l"(src), "r"(sz));
        }
#pragma unroll
        for (int i = 0; i < 4; i++) {
            int q = tid + i * 256;            // 0..1023
            int r = q >> 5;                   // 0..31
            int c = (q & 31) << 2;            // 0..124 step 4
            uint32_t dst = (uint32_t)__cvta_generic_to_shared(Bs + r * BSTR + c);
            const float* src = Bg + (size_t)r * 1024 + c;
            asm volatile("cp.async.cg.shared.global [%0], [%1], 16;\n"
                         :: "r"(dst), "l"(src));
        }
        asm volatile("cp.async.commit_group;\n");
    };

    const int NT = 1024 / BK;   // 32 k-tiles
    load_tile(0, 0);

    for (int kt = 0; kt < NT; kt++) {
        asm volatile("cp.async.wait_group 0;\n");
        __syncthreads();
        if (kt + 1 < NT) load_tile((kt + 1) * BK, (kt + 1) & 1);

        const float* As = sm + (kt & 1) * (ASZ + BSZ);
        const float* Bs = As + ASZ;

#pragma unroll
        for (int kk = 0; kk < BK; kk += 8) {
            uint32_t af[4][4], bf[4][2];
#pragma unroll
            for (int mt = 0; mt < 4; mt++) {
                int rm = wm + mt * 16 + g;
                af[mt][0] = f2tf(As[rm * ASTR + kk + tg]);
                af[mt][1] = f2tf(As[(rm + 8) * ASTR + kk + tg]);
                af[mt][2] = f2tf(As[rm * ASTR + kk + 4 + tg]);
                af[mt][3] = f2tf(As[(rm + 8) * ASTR + kk + 4 + tg]);
            }
#pragma unroll
            for (int nt = 0; nt < 4; nt++) {
                int cn = wn + nt * 8 + g;
                bf[nt][0] = f2tf(Bs[(kk + tg) * BSTR + cn]);
                bf[nt][1] = f2tf(Bs[(kk + 4 + tg) * BSTR + cn]);
            }
#pragma unroll
            for (int mt = 0; mt < 4; mt++)
#pragma unroll
                for (int nt = 0; nt < 4; nt++)
                    mma_tf32(acc[mt][nt], af[mt], bf[nt]);
        }
        // next iteration's wait+sync guarantees compute is done before the
        // buffer gets overwritten, so no trailing barrier needed here
    }

    // epilogue
#pragma unroll
    for (int mt = 0; mt < 4; mt++) {
#pragma unroll
        for (int part = 0; part < 2; part++) {
            int rr = m0 + wm + mt * 16 + g + part * 8;
            if (rr >= M) continue;
            float* crow = C + (size_t)rr * 1024 + n0;
#pragma unroll
            for (int nt = 0; nt < 4; nt++) {
                int cc = wn + nt * 8 + 2 * tg;
                float vx = acc[mt][nt][part * 2 + 0];
                float vy = acc[mt][nt][part * 2 + 1];
                if (flags & FLAG_ACC) {
                    float2 c = *(const float2*)(crow + cc);
                    vx += c.x; vy += c.y;
                }
                if (bias) {
                    vx += bias[n0 + cc];
                    vy += bias[n0 + cc + 1];
                }
                if (flags & FLAG_RELU) {
                    vx = fmaxf(vx, 0.f);
                    vy = fmaxf(vy, 0.f);
                }
                *(float2*)(crow + cc) = make_float2(vx, vy);
            }
        }
    }
}

// ---------------- edge bookkeeping ----------------
__global__ void build_edges_kernel(
    const int* __restrict__ shh, const int* __restrict__ dhh,
    const int* __restrict__ soo, const int* __restrict__ doo,
    const int* __restrict__ sho, const int* __restrict__ dho)
{
    int e = blockIdx.x * blockDim.x + threadIdx.x;
    if (e >= E_TOT) return;
    if (e < E_HH)               { g_esrc[e] = shh[e];             g_edst[e] = dhh[e]; }
    else if (e < E_HH + E_OO)   { g_esrc[e] = soo[e - E_HH];      g_edst[e] = doo[e - E_HH]; }
    else                        { g_esrc[e] = sho[e - E_HH - E_OO]; g_edst[e] = dho[e - E_HH - E_OO]; }
}

__global__ void hist_deg_kernel()
{
    int e = blockIdx.x * blockDim.x + threadIdx.x;
    if (e < E_TOT) atomicAdd(&g_deg[g_edst[e]], 1);
}

__global__ void scan_deg_kernel()
{
    __shared__ int sh[1024];
    int tid = threadIdx.x;
    int carry = 0;
    if (tid == 0) g_off[0] = 0;
    for (int base = 0; base < NN; base += 1024) {
        int i = base + tid;
        int v = (i < NN) ? g_deg[i] : 0;
        sh[tid] = v;
        __syncthreads();
        for (int s = 1; s < 1024; s <<= 1) {
            int t = (tid >= s) ? sh[tid - s] : 0;
            __syncthreads();
            sh[tid] += t;
            __syncthreads();
        }
        if (i < NN) g_off[i + 1] = carry + sh[tid];
        carry += sh[1023];
        __syncthreads();
    }
}

__global__ void copy_cur_kernel()
{
    int i = blockIdx.x * blockDim.x + threadIdx.x;
    if (i < NN) g_cur[i] = g_off[i];
}

__global__ void scatter_kernel()
{
    int e = blockIdx.x * blockDim.x + threadIdx.x;
    if (e >= E_TOT) return;
    int p = atomicAdd(&g_cur[g_edst[e]], 1);
    g_eidx[p] = e;
}

// ---------------- attention logits: a[e] = relu(u+v) . W_att + b --------
__global__ void edge_logits_kernel(const float* __restrict__ W_att,
                                   const float* __restrict__ b_att)
{
    int gw = (blockIdx.x * blockDim.x + threadIdx.x) >> 5;
    int lane = threadIdx.x & 31;
    if (gw >= E_TOT) return;
    int e = gw;
    int src = g_esrc[e], dst = g_edst[e];
    const float *u, *v;
    if (e < E_HH) {
        u = g_u_hh + (size_t)src * DD;
        v = g_v_hh + (size_t)dst * DD;
    } else if (e < E_HH + E_OO) {
        u = g_u_oo + (size_t)(src - NH) * DD;
        v = g_v_oo + (size_t)(dst - NH) * DD;
    } else {
        u = g_u_ho + (size_t)src * DD;
        v = g_v_ho + (size_t)(dst - NH) * DD;
    }
    float sum = 0.f;
    for (int d = lane * 4; d < DD; d += 128) {
        float4 uu = *(const float4*)(u + d);
        float4 vv = *(const float4*)(v + d);
        float4 ww = *(const float4*)(W_att + d);
        sum += fmaxf(uu.x + vv.x, 0.f) * ww.x
             + fmaxf(uu.y + vv.y, 0.f) * ww.y
             + fmaxf(uu.z + vv.z, 0.f) * ww.z
             + fmaxf(uu.w + vv.w, 0.f) * ww.w;
    }
#pragma unroll
    for (int o = 16; o > 0; o >>= 1)
        sum += __shfl_xor_sync(0xffffffffu, sum, o);
    if (lane == 0) g_a[e] = sum + b_att[0];
}

// ---------------- per-dst softmax + weighted aggregation into z ----------
__global__ __launch_bounds__(128) void softmax_z_kernel(const float* __restrict__ n_f)
{
    int n = blockIdx.x;
    int tid = threadIdx.x;
    int s0 = g_off[n], s1 = g_off[n + 1];
    float* zrow = g_z + (size_t)n * DD;

    if (s1 == s0) {
        float4 zf = make_float4(0.f, 0.f, 0.f, 0.f);
        for (int d = tid * 4; d < DD; d += 512)
            *(float4*)(zrow + d) = zf;
        return;
    }

    __shared__ float red[128];

    float m = -1e30f;
    for (int i = s0 + tid; i < s1; i += 128)
        m = fmaxf(m, g_a[g_eidx[i]]);
    red[tid] = m;
    __syncthreads();
    for (int s = 64; s > 0; s >>= 1) {
        if (tid < s) red[tid] = fmaxf(red[tid], red[tid + s]);
        __syncthreads();
    }
    float mx = red[0];
    __syncthreads();

    float se = 0.f;
    for (int i = s0 + tid; i < s1; i += 128)
        se += expf(g_a[g_eidx[i]] - mx);
    red[tid] = se;
    __syncthreads();
    for (int s = 64; s > 0; s >>= 1) {
        if (tid < s) red[tid] += red[tid + s];
        __syncthreads();
    }
    float inv = 1.f / red[0];

    float4 acc0 = make_float4(0.f, 0.f, 0.f, 0.f);
    float4 acc1 = make_float4(0.f, 0.f, 0.f, 0.f);
    for (int i = s0; i < s1; i++) {
        int e = g_eidx[i];
        float w = expf(g_a[e] - mx) * inv;
        const float* row = n_f + (size_t)g_esrc[e] * DD;
        float4 x0 = *(const float4*)(row + tid * 4);
        float4 x1 = *(const float4*)(row + 512 + tid * 4);
        acc0.x += w * x0.x; acc0.y += w * x0.y; acc0.z += w * x0.z; acc0.w += w * x0.w;
        acc1.x += w * x1.x; acc1.y += w * x1.y; acc1.z += w * x1.z; acc1.w += w * x1.w;
    }
    *(float4*)(zrow + tid * 4) = acc0;
    *(float4*)(zrow + 512 + tid * 4) = acc1;
}

// ---------------- launch ----------------
extern "C" void kernel_launch(void* const* d_in, const int* in_sizes, int n_in,
                              void* d_out, int out_size)
{
    const float* n_f    = (const float*)d_in[0];
    const int*   src_hh = (const int*)d_in[1];
    const int*   dst_hh = (const int*)d_in[2];
    const int*   src_oo = (const int*)d_in[3];
    const int*   dst_oo = (const int*)d_in[4];
    const int*   src_ho = (const int*)d_in[5];
    const int*   dst_ho = (const int*)d_in[6];
    const float* W_hh   = (const float*)d_in[7];
    const float* b_hh   = (const float*)d_in[8];
    const float* W_oo   = (const float*)d_in[9];
    const float* b_oo   = (const float*)d_in[10];
    const float* W_ho   = (const float*)d_in[11];
    const float* b_ho   = (const float*)d_in[12];
    const float* W_att  = (const float*)d_in[13];
    const float* b_att  = (const float*)d_in[14];
    const float* W_hn   = (const float*)d_in[15];
    const float* b_hn   = (const float*)d_in[16];
    const float* W_on   = (const float*)d_in[17];
    const float* b_on   = (const float*)d_in[18];
    float* out = (float*)d_out;

    void* p;
    float *u_hh, *v_hh, *u_oo, *v_oo, *u_ho, *v_ho, *z;
    int* deg;
    cudaGetSymbolAddress(&p, g_u_hh); u_hh = (float*)p;
    cudaGetSymbolAddress(&p, g_v_hh); v_hh = (float*)p;
    cudaGetSymbolAddress(&p, g_u_oo); u_oo = (float*)p;
    cudaGetSymbolAddress(&p, g_v_oo); v_oo = (float*)p;
    cudaGetSymbolAddress(&p, g_u_ho); u_ho = (float*)p;
    cudaGetSymbolAddress(&p, g_v_ho); v_ho = (float*)p;
    cudaGetSymbolAddress(&p, g_z);    z    = (float*)p;
    cudaGetSymbolAddress(&p, g_deg);  deg  = (int*)p;

    // opt-in to >48KB dynamic shared memory (idempotent, not a stream op)
    cudaFuncSetAttribute(sgemm_tf32,
                         cudaFuncAttributeMaxDynamicSharedMemorySize, SMEM_BYTES);

    const size_t WOFF = (size_t)DD * DD;   // offset to bottom half of [2D,D] weight
    dim3 thr(256);
    auto grid = [](int M) { return dim3(8, (M + BM - 1) / BM); };

    // node projections: u = A @ W_top ; v = A @ W_bot + b
    sgemm_tf32<<<grid(NH), thr, SMEM_BYTES>>>(n_f,                 W_hh,        u_hh, NH, nullptr, 0);
    sgemm_tf32<<<grid(NH), thr, SMEM_BYTES>>>(n_f,                 W_hh + WOFF, v_hh, NH, b_hh,   0);
    sgemm_tf32<<<grid(NO), thr, SMEM_BYTES>>>(n_f + (size_t)NH*DD, W_oo,        u_oo, NO, nullptr, 0);
    sgemm_tf32<<<grid(NO), thr, SMEM_BYTES>>>(n_f + (size_t)NH*DD, W_oo + WOFF, v_oo, NO, b_oo,   0);
    sgemm_tf32<<<grid(NH), thr, SMEM_BYTES>>>(n_f,                 W_ho,        u_ho, NH, nullptr, 0);
    sgemm_tf32<<<grid(NO), thr, SMEM_BYTES>>>(n_f + (size_t)NH*DD, W_ho + WOFF, v_ho, NO, b_ho,   0);

    // independent: first half of the node-update MLPs (n_f part), into d_out
    sgemm_tf32<<<grid(NH), thr, SMEM_BYTES>>>(n_f,                 W_hn, out,                  NH, nullptr, 0);
    sgemm_tf32<<<grid(NO), thr, SMEM_BYTES>>>(n_f + (size_t)NH*DD, W_on, out + (size_t)NH*DD, NO, nullptr, 0);

    // CSR by destination
    build_edges_kernel<<<(E_TOT + 255) / 256, 256>>>(src_hh, dst_hh, src_oo, dst_oo, src_ho, dst_ho);
    cudaMemsetAsync(deg, 0, NN * sizeof(int));
    hist_deg_kernel<<<(E_TOT + 255) / 256, 256>>>();
    scan_deg_kernel<<<1, 1024>>>();
    copy_cur_kernel<<<(NN + 255) / 256, 256>>>();
    scatter_kernel<<<(E_TOT + 255) / 256, 256>>>();

    // attention logits + softmax-weighted aggregation
    edge_logits_kernel<<<(E_TOT * 32 + 255) / 256, 256>>>(W_att, b_att);
    softmax_z_kernel<<<NN, 128>>>(n_f);

    // second half of the node-update MLPs (z part), accumulate + bias + relu
    sgemm_tf32<<<grid(NH), thr, SMEM_BYTES>>>(z,                 W_hn + WOFF, out,                  NH, b_hn, FLAG_ACC | FLAG_RELU);
    sgemm_tf32<<<grid(NO), thr, SMEM_BYTES>>>(z + (size_t)NH*DD, W_on + WOFF, out + (size_t)NH*DD, NO, b_on, FLAG_ACC | FLAG_RELU);
}